// round 16
// baseline (speedup 1.0000x reference)
#include <cuda_runtime.h>
#include <cstdint>

// LSTM_86440511800183: T=8192 sequential LSTM, H=40, input=1, output=1, batch=1.
// 4 warps (one per SMSP), straight-line step, one bar/step; chain audit matches
// measurement at ~142 cy/step. R15 (re-bench; prior attempt hit broker flake):
// epilogue shfl ordering — g_ gathered BEFORE f_ (g feeds the mul ahead of the
// c-FMA; f feeds the FMA directly), pulling the c-update ~3 cy earlier.
// Everything else identical to the verified R14 winner (1161.3 us).

#define T_MAX 8192
#define HID   40
#define NTH   128   // 4 warps

// d += a * b, packed 2xf32 (SASS FFMA2)
__device__ __forceinline__ void ffma2(uint64_t& d, uint64_t a, uint64_t b) {
    asm("fma.rn.f32x2 %0, %1, %2, %0;" : "+l"(d) : "l"(a), "l"(b));
}
__device__ __forceinline__ uint64_t fadd2(uint64_t a, uint64_t b) {
    uint64_t r;
    asm("add.rn.f32x2 %0, %1, %2;" : "=l"(r) : "l"(a), "l"(b));
    return r;
}
__device__ __forceinline__ void unpack2(float& lo, float& hi, uint64_t v) {
    asm("mov.b64 {%0, %1}, %2;" : "=f"(lo), "=f"(hi) : "l"(v));
}
__device__ __forceinline__ uint64_t pack2(float lo, float hi) {
    uint64_t r;
    asm("mov.b64 %0, {%1, %2};" : "=l"(r) : "f"(lo), "f"(hi));
    return r;
}
// Single-MUFU tanh (sm_75+): measured rel_err ~4e-7 over 8192 steps — safe.
__device__ __forceinline__ float tanhapx(float x) {
    float r; asm("tanh.approx.f32 %0, %1;" : "=f"(r) : "f"(x)); return r;
}

__global__ __launch_bounds__(NTH, 1)
void lstm_seq_kernel(const float* __restrict__ x,
                     const float* __restrict__ W_ih,
                     const float* __restrict__ W_hh,
                     const float* __restrict__ b_ih,
                     const float* __restrict__ b_hh,
                     const float* __restrict__ W_lin,
                     const float* __restrict__ b_lin,
                     float* __restrict__ out,
                     int T)
{
    __shared__ __align__(16) float xs[T_MAX];
    __shared__ __align__(16) float h0f[HID];   // NOTE: xs one-past-end float4
    __shared__ __align__(16) float h1f[HID];   // reads land here (unused vals)

    const int tid  = threadIdx.x;
    const int w    = tid >> 5;
    const int l    = tid & 31;
    const int grp  = l / 10;        // 0:i 1:f 2:g rows; 3: dummy
    const int m    = l % 10;        // unit-in-warp (epilogue unit)
    const int ub   = w * 10;        // warp's unit base (10 units per warp)
    const bool vF  = (l < 30);
    const bool vO  = (l < 10);      // o-row + h-store lanes (their act1 == i)

    for (int i = tid; i < T && i < T_MAX; i += NTH) xs[i] = x[i];

    // ---- full row (gate i/f/g of unit ub+m), pre-scaled for unified act ----
    //   sigmoid rows (i,f): scale .5 -> act = .5*tanh(z/2)+.5 ; tanh row (g): 1.0
    const int   rowF = vF ? (grp * HID + ub + m) : 0;
    const float fsc  = vF ? ((grp == 2) ? 1.0f : 0.5f) : 0.0f;
    uint64_t wf[20];
    {
        const float4* wr = reinterpret_cast<const float4*>(W_hh + rowF * HID);
        #pragma unroll
        for (int k = 0; k < 10; k++) {
            float4 v = wr[k];
            wf[2 * k]     = pack2(v.x * fsc, v.y * fsc);
            wf[2 * k + 1] = pack2(v.z * fsc, v.w * fsc);
        }
    }
    const float wihF  = W_ih[rowF] * fsc;
    const float biasF = (b_ih[rowF] + b_hh[rowF]) * fsc;
    const float AF = (grp == 2) ? 1.0f : 0.5f;
    const float BF = (grp == 2) ? 0.0f : 0.5f;

    // ---- FULL-width o-row of unit ub+l on lanes 0-9 (zeros elsewhere) ------
    const int   rowO = vO ? (3 * HID + ub + l) : 3 * HID;
    const float osc  = vO ? 0.5f : 0.0f;
    uint64_t wo[20];
    {
        const float4* wr = reinterpret_cast<const float4*>(W_hh + rowO * HID);
        #pragma unroll
        for (int k = 0; k < 10; k++) {
            float4 v = wr[k];
            wo[2 * k]     = pack2(v.x * osc, v.y * osc);
            wo[2 * k + 1] = pack2(v.z * osc, v.w * osc);
        }
    }
    const float wihO  = vO ? W_ih[rowO] * 0.5f : 0.0f;
    const float biasO = vO ? (b_ih[rowO] + b_hh[rowO]) * 0.5f : 0.0f;

    if (tid < HID) h0f[tid] = 0.0f;
    float c = 0.0f;   // valid on store lanes 0-9; bounded garbage elsewhere
    __syncthreads();

    const unsigned FULL = 0xffffffffu;
    const ulonglong2* h0v = reinterpret_cast<const ulonglong2*>(h0f);
    const ulonglong2* h1v = reinterpret_cast<const ulonglong2*>(h1f);
    float* const hslot0 = h0f + ub + l;   // hoisted store addresses (lanes 0-9)
    float* const hslot1 = h1f + ub + l;

    auto step = [&](const ulonglong2* __restrict__ hin,
                    float* __restrict__ hslot,
                    uint64_t xpF, uint64_t xpO) {
        // 10 broadcast LDS.128 only (o-dot reuses these registers).
        ulonglong2 hv[10];
        #pragma unroll
        for (int k = 0; k < 10; k++) hv[k] = hin[k];

        // MAIN i/f/g dot: critical chain. 4 packed accumulators, depth 5.
        uint64_t a0 = xpF, a1 = 0ull, a2 = 0ull, a3 = 0ull;
        #pragma unroll
        for (int k = 0; k < 10; k += 2) {
            ffma2(a0, wf[2 * k],     hv[k].x);
            ffma2(a1, wf[2 * k + 1], hv[k].y);
            ffma2(a2, wf[2 * k + 2], hv[k + 1].x);
            ffma2(a3, wf[2 * k + 3], hv[k + 1].y);
        }
        float s0, s1;
        unpack2(s0, s1, fadd2(fadd2(a0, a2), fadd2(a1, a3)));
        float zF   = s0 + s1;
        float act1 = fmaf(AF, tanhapx(zF), BF);   // i/f: sigmoid, g: tanh

        // g_ FIRST: it feeds act1*g_ (mul) ahead of the c-FMA; f_ feeds the
        // FMA directly, so it can arrive 2 cy later at no cost.
        float g_ = __shfl_sync(FULL, act1, 20 + m);
        float f_ = __shfl_sync(FULL, act1, 10 + m);

        // Full-width o-dot (slack path): 4 accumulators, depth 5.
        uint64_t b0 = xpO, b1 = 0ull, b2 = 0ull, b3 = 0ull;
        #pragma unroll
        for (int k = 0; k < 10; k += 2) {
            ffma2(b0, wo[2 * k],     hv[k].x);
            ffma2(b1, wo[2 * k + 1], hv[k].y);
            ffma2(b2, wo[2 * k + 2], hv[k + 1].x);
            ffma2(b3, wo[2 * k + 3], hv[k + 1].y);
        }
        float t0, t1;
        unpack2(t0, t1, fadd2(fadd2(b0, b2), fadd2(b1, b3)));
        float zO   = t0 + t1;
        float act2 = fmaf(0.5f, tanhapx(zO), 0.5f);   // sigmoid(o), local

        float ig = act1 * g_;                         // issues at g_ arrival
        c = fmaf(f_, c, ig);                          // valid on lanes 0-9
        float hval = act2 * tanhapx(c);
        if (vO) *hslot = hval;                        // predicated STS
        __syncthreads();
    };

    // -------- software-pipelined seed flow: seeds for chunk t computed ------
    // -------- during chunk t-4 (in o-dot/MUFU slack), carried in regs  ------
    float4 xv = *reinterpret_cast<const float4*>(xs);   // chunk 0 seeds
    uint64_t F0 = pack2(fmaf(xv.x, wihF, biasF), 0.0f);
    uint64_t O0 = pack2(fmaf(xv.x, wihO, biasO), 0.0f);
    uint64_t F1 = pack2(fmaf(xv.y, wihF, biasF), 0.0f);
    uint64_t O1 = pack2(fmaf(xv.y, wihO, biasO), 0.0f);
    uint64_t F2 = pack2(fmaf(xv.z, wihF, biasF), 0.0f);
    uint64_t O2 = pack2(fmaf(xv.z, wihO, biasO), 0.0f);
    uint64_t F3 = pack2(fmaf(xv.w, wihF, biasF), 0.0f);
    uint64_t O3 = pack2(fmaf(xv.w, wihO, biasO), 0.0f);

    int t = 0;
    for (; t + 4 <= T; t += 4) {
        // Next chunk's xv: issued at chunk start, latency hidden across steps.
        // One-past-end read at the last chunk stays inside this smem block
        // (lands in h0f/h1f); the values are never used.
        float4 xvn = *reinterpret_cast<const float4*>(xs + t + 4);

        step(h0v, hslot1, F0, O0);
        step(h1v, hslot0, F1, O1);

        // Next chunk's seeds: computed mid-chunk, in slack, off post-bar path.
        uint64_t F0n = pack2(fmaf(xvn.x, wihF, biasF), 0.0f);
        uint64_t O0n = pack2(fmaf(xvn.x, wihO, biasO), 0.0f);
        uint64_t F1n = pack2(fmaf(xvn.y, wihF, biasF), 0.0f);
        uint64_t O1n = pack2(fmaf(xvn.y, wihO, biasO), 0.0f);
        uint64_t F2n = pack2(fmaf(xvn.z, wihF, biasF), 0.0f);
        uint64_t O2n = pack2(fmaf(xvn.z, wihO, biasO), 0.0f);
        uint64_t F3n = pack2(fmaf(xvn.w, wihF, biasF), 0.0f);
        uint64_t O3n = pack2(fmaf(xvn.w, wihO, biasO), 0.0f);

        step(h0v, hslot1, F2, O2);
        step(h1v, hslot0, F3, O3);

        F0 = F0n; O0 = O0n; F1 = F1n; O1 = O1n;
        F2 = F2n; O2 = O2n; F3 = F3n; O3 = O3n;
    }
    int p = 0;
    for (; t < T; t++) {
        uint64_t Fp = pack2(fmaf(xs[t], wihF, biasF), 0.0f);
        uint64_t Op = pack2(fmaf(xs[t], wihO, biasO), 0.0f);
        if (p == 0) step(h0v, hslot1, Fp, Op);
        else        step(h1v, hslot0, Fp, Op);
        p ^= 1;
    }
    const float* hf = (p == 0) ? h0f : h1f;

    if (tid == 0) {
        float sum = b_lin[0];
        #pragma unroll
        for (int k = 0; k < HID; k++) sum = fmaf(hf[k], W_lin[k], sum);
        out[0] = sum;
    }
}

extern "C" void kernel_launch(void* const* d_in, const int* in_sizes, int n_in,
                              void* d_out, int out_size)
{
    const float* x     = (const float*)d_in[0]; // input_seq [T,1]
    const float* W_ih  = (const float*)d_in[1]; // [160,1]
    const float* W_hh  = (const float*)d_in[2]; // [160,40]
    const float* b_ih  = (const float*)d_in[3]; // [160]
    const float* b_hh  = (const float*)d_in[4]; // [160]
    const float* W_lin = (const float*)d_in[5]; // [1,40]
    const float* b_lin = (const float*)d_in[6]; // [1]
    float* out = (float*)d_out;

    int T = in_sizes[0];
    lstm_seq_kernel<<<1, NTH>>>(x, W_ih, W_hh, b_ih, b_hh, W_lin, b_lin, out, T);
}